// round 11
// baseline (speedup 1.0000x reference)
#include <cuda_runtime.h>
#include <cuda.h>
#include <cuda_fp16.h>
#include <stdint.h>
#include <math.h>

#define VS 4096
#define HS 2048
#define NB 64
#define STEPS 100
#define SPLIT_H 16
#define SPLIT_V 8
#define KTOT (VS + HS)

#define MT 128        // M tile per CTA
#define BKT 64        // K per tile (64 halves = 128B rows, SW128)
#define NSTAGE 2
#define WSCALE 64.0f
#define INV_WSCALE (1.0f/64.0f)

#define A_LIMB_BYTES (MT * BKT * 2)            // 16384
#define B_LIMB_BYTES (NB * BKT * 2)            // 8192
#define STAGE_BYTES  (2*A_LIMB_BYTES + 2*B_LIMB_BYTES)  // 49152

// ---------------- device scratch ----------------
__device__ __align__(1024) __half g_Wv0[(size_t)VS*KTOT], g_Wv1[(size_t)VS*KTOT]; // [v][vv|vh]
__device__ __align__(1024) __half g_Wh0[(size_t)HS*KTOT], g_Wh1[(size_t)HS*KTOT]; // [h][vht|hh]
__device__ __align__(1024) __half g_S0[NB*KTOT], g_S1[NB*KTOT];                   // [b][vis|hid]
__device__ float g_visF[VS*NB], g_hidF[HS*NB];     // fp32 state [feature][batch]
__device__ float g_D1[SPLIT_H*HS*NB];
__device__ float g_D2[SPLIT_V*VS*NB];

// ---------------- helpers ----------------
__device__ __forceinline__ uint32_t smaddr(const void* p) {
    return (uint32_t)__cvta_generic_to_shared(p);
}
__device__ __forceinline__ void split_w(float w, __half& h0, __half& h1) {
    float ws = w * WSCALE;
    h0 = __float2half_rn(ws);
    h1 = __float2half_rn(ws - __half2float(h0));
}
__device__ __forceinline__ uint32_t swz(uint32_t off) {  // SW128 swizzle
    return off ^ ((off >> 3) & 0x70);
}
__device__ __forceinline__ void tma2d(uint32_t dst, const CUtensorMap* map,
                                      int x, int y, uint32_t mb) {
    asm volatile(
        "cp.async.bulk.tensor.2d.shared::cta.global.tile.mbarrier::complete_tx::bytes "
        "[%0], [%1, {%2, %3}], [%4];"
        :: "r"(dst), "l"(map), "r"(x), "r"(y), "r"(mb) : "memory");
}
__device__ __forceinline__ void mbar_wait(uint32_t mb, int phase) {
    asm volatile(
        "{\n\t.reg .pred P;\n\t"
        "W_%=:\n\t"
        "mbarrier.try_wait.parity.acquire.cta.shared::cta.b64 P, [%0], %1, 0x989680;\n\t"
        "@P bra.uni D_%=;\n\t"
        "bra.uni W_%=;\n\t"
        "D_%=:\n\t}"
        :: "r"(mb), "r"(phase) : "memory");
}

#define MMA_F32(dd, aa, b0r, b1r)                                            \
    asm volatile("mma.sync.aligned.m16n8k16.row.col.f32.f16.f16.f32 "        \
        "{%0,%1,%2,%3},{%4,%5,%6,%7},{%8,%9},{%0,%1,%2,%3};"                 \
        : "+f"(dd[0]), "+f"(dd[1]), "+f"(dd[2]), "+f"(dd[3])                 \
        : "r"(aa[0]), "r"(aa[1]), "r"(aa[2]), "r"(aa[3]), "r"(b0r), "r"(b1r))

#define MMA_F16(cc, aa, b0r, b1r)                                            \
    asm volatile("mma.sync.aligned.m16n8k16.row.col.f16.f16.f16.f16 "        \
        "{%0,%1},{%2,%3,%4,%5},{%6,%7},{%0,%1};"                             \
        : "+r"(cc[0]), "+r"(cc[1])                                           \
        : "r"(aa[0]), "r"(aa[1]), "r"(aa[2]), "r"(aa[3]), "r"(b0r), "r"(b1r))

// ---------------- prep kernels ----------------
__global__ void k_sym_split(const float* __restrict__ raw, int n,
                            __half* __restrict__ o0, __half* __restrict__ o1,
                            int colOff) {
    __shared__ float tA[32][33], tB[32][33];
    int bi = blockIdx.y * 32, bj = blockIdx.x * 32;
    int tx = threadIdx.x, ty = threadIdx.y;
#pragma unroll
    for (int j = 0; j < 32; j += 8) {
        tA[ty + j][tx] = raw[(size_t)(bi + ty + j) * n + bj + tx];
        tB[ty + j][tx] = raw[(size_t)(bj + ty + j) * n + bi + tx];
    }
    __syncthreads();
#pragma unroll
    for (int j = 0; j < 32; j += 8) {
        int i = bi + ty + j, jj = bj + tx;
        float wv = (i < jj) ? tA[ty + j][tx] : ((i > jj) ? tB[tx][ty + j] : 0.0f);
        __half h0, h1; split_w(wv, h0, h1);
        o0[(size_t)i * KTOT + colOff + jj] = h0;
        o1[(size_t)i * KTOT + colOff + jj] = h1;
    }
}

__global__ void k_vh_split(const float* __restrict__ vh,
                           __half* __restrict__ wv0, __half* __restrict__ wv1,
                           __half* __restrict__ wh0, __half* __restrict__ wh1) {
    __shared__ float tile[32][33];
    int bh = blockIdx.x * 32, bv = blockIdx.y * 32;
    int tx = threadIdx.x, ty = threadIdx.y;
#pragma unroll
    for (int j = 0; j < 32; j += 8)
        tile[ty + j][tx] = vh[(size_t)(bv + ty + j) * HS + bh + tx];
    __syncthreads();
#pragma unroll
    for (int j = 0; j < 32; j += 8) {
        __half h0, h1;
        split_w(tile[ty + j][tx], h0, h1);
        wv0[(size_t)(bv + ty + j) * KTOT + VS + bh + tx] = h0;
        wv1[(size_t)(bv + ty + j) * KTOT + VS + bh + tx] = h1;
        split_w(tile[tx][ty + j], h0, h1);
        wh0[(size_t)(bh + ty + j) * KTOT + bv + tx] = h0;
        wh1[(size_t)(bh + ty + j) * KTOT + bv + tx] = h1;
    }
}

__global__ void k_init(const float* __restrict__ x,
                       float* __restrict__ visF, float* __restrict__ hidF,
                       __half* __restrict__ S0, __half* __restrict__ S1) {
    int idx = blockIdx.x * blockDim.x + threadIdx.x;
    if (idx < NB * VS) {
        int b = idx >> 12, v = idx & (VS - 1);
        float val = x[idx];
        visF[v * NB + b] = val;
        __half h0 = __float2half_rn(val);
        __half h1 = __float2half_rn(val - __half2float(h0));
        S0[(size_t)b * KTOT + v] = h0;
        S1[(size_t)b * KTOT + v] = h1;
    }
    if (idx < NB * HS) {
        int b = idx >> 11, h = idx & (HS - 1);
        hidF[idx] = 0.5f;
        S0[(size_t)b * KTOT + VS + h] = __float2half_rn(0.5f);
        S1[(size_t)b * KTOT + VS + h] = __float2half_rn(0.0f);
    }
}

// ---------------- TMA-fed split-fp16 GEMM ----------------
// Main product f32-accum MMA; correction products f16-accum MMA (2x rate),
// flushed exactly into fp32 accumulators once per 64-K tile.
__global__ __launch_bounds__(256, 2)
void gemm_tma(const __grid_constant__ CUtensorMap mA0,
              const __grid_constant__ CUtensorMap mA1,
              const __grid_constant__ CUtensorMap mB0,
              const __grid_constant__ CUtensorMap mB1,
              float* __restrict__ Cbuf, int Mtot, int kPerSlice) {
    extern __shared__ __align__(128) unsigned char smraw[];
    uint64_t* mbar = (uint64_t*)smraw;                // NSTAGE mbarriers
    unsigned char* data = smraw + 1024;

    const int tid = threadIdx.x;
    const int lane = tid & 31;
    const int w = tid >> 5;
    const int wm = (w & 3) * 32;
    const int wn = (w >> 2) * 32;
    const int m_blk = blockIdx.x * MT;
    const int kbeg = blockIdx.z * kPerSlice;
    const int ntiles = kPerSlice / BKT;

    if (tid == 0) {
#pragma unroll
        for (int s = 0; s < NSTAGE; s++)
            asm volatile("mbarrier.init.shared.b64 [%0], 1;"
                         :: "r"(smaddr(mbar + s)) : "memory");
        asm volatile("fence.proxy.async.shared::cta;" ::: "memory");
    }
    __syncthreads();

    auto issue = [&](int t, int st) {
        uint32_t mb = smaddr(mbar + st);
        asm volatile("mbarrier.arrive.expect_tx.shared.b64 _, [%0], %1;"
                     :: "r"(mb), "r"((uint32_t)STAGE_BYTES) : "memory");
        unsigned char* sp = data + (size_t)st * STAGE_BYTES;
        int kx = kbeg + t * BKT;
        tma2d(smaddr(sp),                                   &mA0, kx, m_blk, mb);
        tma2d(smaddr(sp + A_LIMB_BYTES),                    &mA1, kx, m_blk, mb);
        tma2d(smaddr(sp + 2*A_LIMB_BYTES),                  &mB0, kx, 0,     mb);
        tma2d(smaddr(sp + 2*A_LIMB_BYTES + B_LIMB_BYTES),   &mB1, kx, 0,     mb);
    };

    if (tid == 0) {
        issue(0, 0);
        if (ntiles > 1) issue(1, 1);
    }

    float d[2][4][4];
#pragma unroll
    for (int i = 0; i < 2; i++)
#pragma unroll
        for (int j = 0; j < 4; j++)
#pragma unroll
            for (int q = 0; q < 4; q++) d[i][j][q] = 0.0f;

    for (int t = 0; t < ntiles; t++) {
        int st = t & 1;
        int ph = (t >> 1) & 1;
        mbar_wait(smaddr(mbar + st), ph);

        const unsigned char* sp = data + (size_t)st * STAGE_BYTES;
        const unsigned char* A0s = sp;
        const unsigned char* A1s = sp + A_LIMB_BYTES;
        const unsigned char* B0s = sp + 2*A_LIMB_BYTES;
        const unsigned char* B1s = B0s + B_LIMB_BYTES;

        // per-tile f16 correction accumulators
        uint32_t c16[2][4][2];
#pragma unroll
        for (int i = 0; i < 2; i++)
#pragma unroll
            for (int j = 0; j < 4; j++) { c16[i][j][0] = 0; c16[i][j][1] = 0; }

#pragma unroll
        for (int ks = 0; ks < BKT; ks += 16) {
            uint32_t af[2][2][4];   // [mtile][limb][4]
#pragma unroll
            for (int mt = 0; mt < 2; mt++) {
                int row = wm + mt * 16 + ((lane >> 3) & 1) * 8 + (lane & 7);
                uint32_t off = swz((uint32_t)row * 128 + (ks + (lane >> 4) * 8) * 2);
                uint32_t a0 = smaddr(A0s + off);
                asm volatile("ldmatrix.sync.aligned.m8n8.x4.shared.b16 {%0,%1,%2,%3},[%4];"
                    : "=r"(af[mt][0][0]), "=r"(af[mt][0][1]),
                      "=r"(af[mt][0][2]), "=r"(af[mt][0][3]) : "r"(a0));
                uint32_t a1 = smaddr(A1s + off);
                asm volatile("ldmatrix.sync.aligned.m8n8.x4.shared.b16 {%0,%1,%2,%3},[%4];"
                    : "=r"(af[mt][1][0]), "=r"(af[mt][1][1]),
                      "=r"(af[mt][1][2]), "=r"(af[mt][1][3]) : "r"(a1));
            }
            uint32_t bf[2][8];      // [limb][nt*4 + r]
#pragma unroll
            for (int nt = 0; nt < 2; nt++) {
                int row = wn + nt * 16 + (lane >> 4) * 8 + (lane & 7);
                uint32_t off = swz((uint32_t)row * 128 + (ks + ((lane >> 3) & 1) * 8) * 2);
                uint32_t b0 = smaddr(B0s + off);
                asm volatile("ldmatrix.sync.aligned.m8n8.x4.shared.b16 {%0,%1,%2,%3},[%4];"
                    : "=r"(bf[0][nt * 4 + 0]), "=r"(bf[0][nt * 4 + 1]),
                      "=r"(bf[0][nt * 4 + 2]), "=r"(bf[0][nt * 4 + 3]) : "r"(b0));
                uint32_t b1 = smaddr(B1s + off);
                asm volatile("ldmatrix.sync.aligned.m8n8.x4.shared.b16 {%0,%1,%2,%3},[%4];"
                    : "=r"(bf[1][nt * 4 + 0]), "=r"(bf[1][nt * 4 + 1]),
                      "=r"(bf[1][nt * 4 + 2]), "=r"(bf[1][nt * 4 + 3]) : "r"(b1));
            }
#pragma unroll
            for (int mt = 0; mt < 2; mt++) {
#pragma unroll
                for (int j = 0; j < 4; j++) {
                    uint32_t b00 = bf[0][j * 2], b01 = bf[0][j * 2 + 1];
                    uint32_t b10 = bf[1][j * 2], b11 = bf[1][j * 2 + 1];
                    MMA_F32(d[mt][j], af[mt][0], b00, b01);    // w0*b0 (f32 acc)
                    MMA_F16(c16[mt][j], af[mt][0], b10, b11);  // w0*b1 (f16 acc)
                    MMA_F16(c16[mt][j], af[mt][1], b00, b01);  // w1*b0 (f16 acc)
                }
            }
        }
        // flush f16 corrections into fp32 accumulators
#pragma unroll
        for (int mt = 0; mt < 2; mt++) {
#pragma unroll
            for (int j = 0; j < 4; j++) {
                float2 f0 = __half22float2(*(__half2*)&c16[mt][j][0]);
                float2 f1 = __half22float2(*(__half2*)&c16[mt][j][1]);
                d[mt][j][0] += f0.x; d[mt][j][1] += f0.y;
                d[mt][j][2] += f1.x; d[mt][j][3] += f1.y;
            }
        }
        __syncthreads();
        if (tid == 0 && t + NSTAGE < ntiles) issue(t + NSTAGE, st);
    }

    float* Cz = Cbuf + (size_t)blockIdx.z * Mtot * NB;
#pragma unroll
    for (int mt = 0; mt < 2; mt++) {
#pragma unroll
        for (int j = 0; j < 4; j++) {
            int r = m_blk + wm + mt * 16 + (lane >> 2);
            int c = wn + j * 8 + (lane & 3) * 2;
            *(float2*)&Cz[(size_t)r * NB + c]       = make_float2(d[mt][j][0], d[mt][j][1]);
            *(float2*)&Cz[(size_t)(r + 8) * NB + c] = make_float2(d[mt][j][2], d[mt][j][3]);
        }
    }
}

// ---------------- epilogue (two-phase, proven in R10) ----------------
__global__ __launch_bounds__(256)
void epi(const float* __restrict__ Cbuf, int S, int F,
         const float* __restrict__ bias,
         float* __restrict__ stateF,
         __half* __restrict__ S0, __half* __restrict__ S1, int colBase,
         int step, const int* __restrict__ steps_ptr,
         float* __restrict__ finout) {
    __shared__ float nvs[16][65];
    const int t = threadIdx.x;
    const int f0 = blockIdx.x * 16;

    float stepsf = (float)(*steps_ptr);
    float temp = 0.01f * (1.0f + 4.0f * expf((-5.0f * (float)step) / stepsf));

    {
        int fl = t >> 4;
        int b4 = (t & 15) * 4;
        int f = f0 + fl;
        const float* cb = Cbuf + (size_t)f * NB + b4;
        float4 s = make_float4(0.f, 0.f, 0.f, 0.f);
        for (int z = 0; z < S; z++) {
            float4 v = *(const float4*)(cb + (size_t)z * F * NB);
            s.x += v.x; s.y += v.y; s.z += v.z; s.w += v.w;
        }
        float bi = bias[f];
        s.x = s.x * INV_WSCALE + bi; s.y = s.y * INV_WSCALE + bi;
        s.z = s.z * INV_WSCALE + bi; s.w = s.w * INV_WSCALE + bi;
        float4 old = *(const float4*)&stateF[(size_t)f * NB + b4];
        float4 nv;
        nv.x = 0.9f * old.x + 0.1f / (1.0f + expf(-s.x / temp));
        nv.y = 0.9f * old.y + 0.1f / (1.0f + expf(-s.y / temp));
        nv.z = 0.9f * old.z + 0.1f / (1.0f + expf(-s.z / temp));
        nv.w = 0.9f * old.w + 0.1f / (1.0f + expf(-s.w / temp));
        *(float4*)&stateF[(size_t)f * NB + b4] = nv;
        nvs[fl][b4 + 0] = nv.x;
        nvs[fl][b4 + 1] = nv.y;
        nvs[fl][b4 + 2] = nv.z;
        nvs[fl][b4 + 3] = nv.w;
    }
    __syncthreads();

    {
        int b = t >> 2;
        int fo = (t & 3) * 4;
        float v0 = nvs[fo + 0][b], v1 = nvs[fo + 1][b];
        float v2 = nvs[fo + 2][b], v3 = nvs[fo + 3][b];
        __half h00 = __float2half_rn(v0), h01 = __float2half_rn(v1);
        __half h02 = __float2half_rn(v2), h03 = __float2half_rn(v3);
        __half r0 = __float2half_rn(v0 - __half2float(h00));
        __half r1 = __float2half_rn(v1 - __half2float(h01));
        __half r2 = __float2half_rn(v2 - __half2float(h02));
        __half r3 = __float2half_rn(v3 - __half2float(h03));
        size_t base = (size_t)b * KTOT + colBase + f0 + fo;
        *(__half2*)&S0[base]     = __halves2half2(h00, h01);
        *(__half2*)&S0[base + 2] = __halves2half2(h02, h03);
        *(__half2*)&S1[base]     = __halves2half2(r0, r1);
        *(__half2*)&S1[base + 2] = __halves2half2(r2, r3);
        if (finout) {
            *(float4*)&finout[(size_t)b * F + f0 + fo] = make_float4(v0, v1, v2, v3);
        }
    }
}

// ---------------- host: tensor map encode ----------------
typedef CUresult (*EncodeTiledFn)(
    CUtensorMap*, CUtensorMapDataType, cuuint32_t, void*,
    const cuuint64_t*, const cuuint64_t*, const cuuint32_t*, const cuuint32_t*,
    CUtensorMapInterleave, CUtensorMapSwizzle, CUtensorMapL2promotion,
    CUtensorMapFloatOOBfill);

static EncodeTiledFn get_encoder() {
    void* fp = nullptr;
#if CUDART_VERSION >= 12050
    cudaDriverEntryPointQueryResult st;
    cudaGetDriverEntryPointByVersion("cuTensorMapEncodeTiled", &fp, 12000,
                                     cudaEnableDefault, &st);
#else
    cudaDriverEntryPointQueryResult st;
    cudaGetDriverEntryPoint("cuTensorMapEncodeTiled", &fp, cudaEnableDefault, &st);
#endif
    return (EncodeTiledFn)fp;
}

static void make_map(EncodeTiledFn enc, CUtensorMap* m, void* ptr,
                     uint64_t rows, uint32_t boxRows) {
    cuuint64_t dims[2]    = {(cuuint64_t)KTOT, (cuuint64_t)rows};
    cuuint64_t strides[1] = {(cuuint64_t)KTOT * sizeof(__half)};
    cuuint32_t box[2]     = {BKT, boxRows};
    cuuint32_t es[2]      = {1, 1};
    enc(m, CU_TENSOR_MAP_DATA_TYPE_FLOAT16, 2, ptr, dims, strides, box, es,
        CU_TENSOR_MAP_INTERLEAVE_NONE, CU_TENSOR_MAP_SWIZZLE_128B,
        CU_TENSOR_MAP_L2_PROMOTION_L2_128B, CU_TENSOR_MAP_FLOAT_OOB_FILL_NONE);
}

// ---------------- host launcher ----------------
extern "C" void kernel_launch(void* const* d_in, const int* in_sizes, int n_in,
                              void* d_out, int out_size) {
    const float* x        = (const float*)d_in[0];
    const float* vis_bias = (const float*)d_in[1];
    const float* hid_bias = (const float*)d_in[2];
    const float* vis_hid  = (const float*)d_in[3];
    const float* vv_raw   = (const float*)d_in[4];
    const float* hh_raw   = (const float*)d_in[5];
    const int*   steps_p  = (const int*)d_in[6];

    __half *Wv0, *Wv1, *Wh0, *Wh1, *S0, *S1;
    float *visF, *hidF, *D1, *D2;
    cudaGetSymbolAddress((void**)&Wv0, g_Wv0); cudaGetSymbolAddress((void**)&Wv1, g_Wv1);
    cudaGetSymbolAddress((void**)&Wh0, g_Wh0); cudaGetSymbolAddress((void**)&Wh1, g_Wh1);
    cudaGetSymbolAddress((void**)&S0, g_S0);   cudaGetSymbolAddress((void**)&S1, g_S1);
    cudaGetSymbolAddress((void**)&visF, g_visF); cudaGetSymbolAddress((void**)&hidF, g_hidF);
    cudaGetSymbolAddress((void**)&D1, g_D1);   cudaGetSymbolAddress((void**)&D2, g_D2);

    EncodeTiledFn enc = get_encoder();
    CUtensorMap mWv0, mWv1, mWh0, mWh1, mS0, mS1;
    make_map(enc, &mWv0, Wv0, VS, MT);
    make_map(enc, &mWv1, Wv1, VS, MT);
    make_map(enc, &mWh0, Wh0, HS, MT);
    make_map(enc, &mWh1, Wh1, HS, MT);
    make_map(enc, &mS0,  S0,  NB, NB);
    make_map(enc, &mS1,  S1,  NB, NB);

    const int SMEM = 1024 + NSTAGE * STAGE_BYTES;   // 99328
    cudaFuncSetAttribute(gemm_tma, cudaFuncAttributeMaxDynamicSharedMemorySize, SMEM);

    k_sym_split<<<dim3(VS / 32, VS / 32), dim3(32, 8)>>>(vv_raw, VS, Wv0, Wv1, 0);
    k_sym_split<<<dim3(HS / 32, HS / 32), dim3(32, 8)>>>(hh_raw, HS, Wh0, Wh1, VS);
    k_vh_split<<<dim3(HS / 32, VS / 32), dim3(32, 8)>>>(vis_hid, Wv0, Wv1, Wh0, Wh1);
    k_init<<<(NB * VS + 255) / 256, 256>>>(x, visF, hidF, S0, S1);

    for (int i = 0; i < STEPS; i++) {
        // hidden update
        gemm_tma<<<dim3(HS / MT, 1, SPLIT_H), 256, SMEM>>>(
            mWh0, mWh1, mS0, mS1, D1, HS, KTOT / SPLIT_H);
        epi<<<HS / 16, 256>>>(
            D1, SPLIT_H, HS, hid_bias, hidF, S0, S1, VS, i, steps_p, nullptr);

        // visible update
        gemm_tma<<<dim3(VS / MT, 1, SPLIT_V), 256, SMEM>>>(
            mWv0, mWv1, mS0, mS1, D2, VS, KTOT / SPLIT_V);
        epi<<<VS / 16, 256>>>(
            D2, SPLIT_V, VS, vis_bias, visF, S0, S1, 0, i, steps_p,
            (i == STEPS - 1) ? (float*)d_out : nullptr);
    }
}

// round 14
// speedup vs baseline: 1.0334x; 1.0334x over previous
#include <cuda_runtime.h>
#include <cuda.h>
#include <cuda_fp16.h>
#include <stdint.h>
#include <math.h>

#define VS 4096
#define HS 2048
#define NB 64
#define STEPS 100
#define SPLIT_H 16
#define SPLIT_V 8
#define KTOT (VS + HS)

#define MT 128        // M tile per CTA
#define BKT 64        // K per tile (64 halves = 128B rows, SW128)
#define NSTAGE 2
#define WSCALE 64.0f
#define INV_WSCALE (1.0f/64.0f)

#define A_LIMB_BYTES (MT * BKT * 2)            // 16384
#define B_LIMB_BYTES (NB * BKT * 2)            // 8192
#define STAGE_BYTES  (2*A_LIMB_BYTES + 2*B_LIMB_BYTES)  // 49152

// ---------------- device scratch ----------------
__device__ __align__(1024) __half g_Wv0[(size_t)VS*KTOT], g_Wv1[(size_t)VS*KTOT]; // [v][vv|vh]
__device__ __align__(1024) __half g_Wh0[(size_t)HS*KTOT], g_Wh1[(size_t)HS*KTOT]; // [h][vht|hh]
__device__ __align__(1024) __half g_S0[NB*KTOT], g_S1[NB*KTOT];                   // [b][vis|hid]
__device__ float g_visF[VS*NB], g_hidF[HS*NB];     // fp32 state [feature][batch]
__device__ float g_D1[SPLIT_H*HS*NB];
__device__ float g_D2[SPLIT_V*VS*NB];

// ---------------- helpers ----------------
__device__ __forceinline__ uint32_t smaddr(const void* p) {
    return (uint32_t)__cvta_generic_to_shared(p);
}
__device__ __forceinline__ void split_w(float w, __half& h0, __half& h1) {
    float ws = w * WSCALE;
    h0 = __float2half_rn(ws);
    h1 = __float2half_rn(ws - __half2float(h0));
}
__device__ __forceinline__ uint32_t swz(uint32_t off) {  // SW128 swizzle
    return off ^ ((off >> 3) & 0x70);
}
__device__ __forceinline__ void tma2d(uint32_t dst, const CUtensorMap* map,
                                      int x, int y, uint32_t mb) {
    asm volatile(
        "cp.async.bulk.tensor.2d.shared::cta.global.tile.mbarrier::complete_tx::bytes "
        "[%0], [%1, {%2, %3}], [%4];"
        :: "r"(dst), "l"(map), "r"(x), "r"(y), "r"(mb) : "memory");
}
__device__ __forceinline__ void mbar_wait(uint32_t mb, int phase) {
    asm volatile(
        "{\n\t.reg .pred P;\n\t"
        "W_%=:\n\t"
        "mbarrier.try_wait.parity.acquire.cta.shared::cta.b64 P, [%0], %1, 0x989680;\n\t"
        "@P bra.uni D_%=;\n\t"
        "bra.uni W_%=;\n\t"
        "D_%=:\n\t}"
        :: "r"(mb), "r"(phase) : "memory");
}
__device__ __forceinline__ void pdl_wait() {
    asm volatile("griddepcontrol.wait;" ::: "memory");
}
__device__ __forceinline__ void pdl_trigger() {
    asm volatile("griddepcontrol.launch_dependents;" ::: "memory");
}

#define MMA_16816(dd, aa, b0r, b1r)                                          \
    asm volatile("mma.sync.aligned.m16n8k16.row.col.f32.f16.f16.f32 "        \
        "{%0,%1,%2,%3},{%4,%5,%6,%7},{%8,%9},{%0,%1,%2,%3};"                 \
        : "+f"(dd[0]), "+f"(dd[1]), "+f"(dd[2]), "+f"(dd[3])                 \
        : "r"(aa[0]), "r"(aa[1]), "r"(aa[2]), "r"(aa[3]), "r"(b0r), "r"(b1r))

// ---------------- prep kernels ----------------
__global__ void k_sym_split(const float* __restrict__ raw, int n,
                            __half* __restrict__ o0, __half* __restrict__ o1,
                            int colOff) {
    __shared__ float tA[32][33], tB[32][33];
    int bi = blockIdx.y * 32, bj = blockIdx.x * 32;
    int tx = threadIdx.x, ty = threadIdx.y;
#pragma unroll
    for (int j = 0; j < 32; j += 8) {
        tA[ty + j][tx] = raw[(size_t)(bi + ty + j) * n + bj + tx];
        tB[ty + j][tx] = raw[(size_t)(bj + ty + j) * n + bi + tx];
    }
    __syncthreads();
#pragma unroll
    for (int j = 0; j < 32; j += 8) {
        int i = bi + ty + j, jj = bj + tx;
        float wv = (i < jj) ? tA[ty + j][tx] : ((i > jj) ? tB[tx][ty + j] : 0.0f);
        __half h0, h1; split_w(wv, h0, h1);
        o0[(size_t)i * KTOT + colOff + jj] = h0;
        o1[(size_t)i * KTOT + colOff + jj] = h1;
    }
}

__global__ void k_vh_split(const float* __restrict__ vh,
                           __half* __restrict__ wv0, __half* __restrict__ wv1,
                           __half* __restrict__ wh0, __half* __restrict__ wh1) {
    __shared__ float tile[32][33];
    int bh = blockIdx.x * 32, bv = blockIdx.y * 32;
    int tx = threadIdx.x, ty = threadIdx.y;
#pragma unroll
    for (int j = 0; j < 32; j += 8)
        tile[ty + j][tx] = vh[(size_t)(bv + ty + j) * HS + bh + tx];
    __syncthreads();
#pragma unroll
    for (int j = 0; j < 32; j += 8) {
        __half h0, h1;
        split_w(tile[ty + j][tx], h0, h1);
        wv0[(size_t)(bv + ty + j) * KTOT + VS + bh + tx] = h0;
        wv1[(size_t)(bv + ty + j) * KTOT + VS + bh + tx] = h1;
        split_w(tile[tx][ty + j], h0, h1);
        wh0[(size_t)(bh + ty + j) * KTOT + bv + tx] = h0;
        wh1[(size_t)(bh + ty + j) * KTOT + bv + tx] = h1;
    }
}

__global__ void k_init(const float* __restrict__ x,
                       float* __restrict__ visF, float* __restrict__ hidF,
                       __half* __restrict__ S0, __half* __restrict__ S1) {
    int idx = blockIdx.x * blockDim.x + threadIdx.x;
    if (idx < NB * VS) {
        int b = idx >> 12, v = idx & (VS - 1);
        float val = x[idx];
        visF[v * NB + b] = val;
        __half h0 = __float2half_rn(val);
        __half h1 = __float2half_rn(val - __half2float(h0));
        S0[(size_t)b * KTOT + v] = h0;
        S1[(size_t)b * KTOT + v] = h1;
    }
    if (idx < NB * HS) {
        int b = idx >> 11, h = idx & (HS - 1);
        hidF[idx] = 0.5f;
        S0[(size_t)b * KTOT + VS + h] = __float2half_rn(0.5f);
        S1[(size_t)b * KTOT + VS + h] = __float2half_rn(0.0f);
    }
}

// ---------------- TMA-fed split-fp16 GEMM (R10 arithmetic + PDL) ----------
__global__ __launch_bounds__(256, 2)
void gemm_tma(const __grid_constant__ CUtensorMap mA0,
              const __grid_constant__ CUtensorMap mA1,
              const __grid_constant__ CUtensorMap mB0,
              const __grid_constant__ CUtensorMap mB1,
              float* __restrict__ Cbuf, int Mtot, int kPerSlice) {
    extern __shared__ __align__(128) unsigned char smraw[];
    uint64_t* mbar = (uint64_t*)smraw;                // NSTAGE mbarriers
    unsigned char* data = smraw + 1024;

    const int tid = threadIdx.x;
    const int lane = tid & 31;
    const int w = tid >> 5;
    const int wm = (w & 3) * 32;
    const int wn = (w >> 2) * 32;
    const int m_blk = blockIdx.x * MT;
    const int kbeg = blockIdx.z * kPerSlice;
    const int ntiles = kPerSlice / BKT;   // always >= 2 here

    if (tid == 0) {
#pragma unroll
        for (int s = 0; s < NSTAGE; s++)
            asm volatile("mbarrier.init.shared.b64 [%0], 1;"
                         :: "r"(smaddr(mbar + s)) : "memory");
        asm volatile("fence.proxy.async.shared::cta;" ::: "memory");
    }
    __syncthreads();

    // PDL prologue: prefetch immutable WEIGHT tiles for both stages, then
    // wait for the upstream kernel before touching the state limbs.
    if (tid == 0) {
#pragma unroll
        for (int t = 0; t < NSTAGE; t++) {
            uint32_t mb = smaddr(mbar + t);
            asm volatile("mbarrier.arrive.expect_tx.shared.b64 _, [%0], %1;"
                         :: "r"(mb), "r"((uint32_t)STAGE_BYTES) : "memory");
            unsigned char* sp = data + (size_t)t * STAGE_BYTES;
            int kx = kbeg + t * BKT;
            tma2d(smaddr(sp),                &mA0, kx, m_blk, mb);
            tma2d(smaddr(sp + A_LIMB_BYTES), &mA1, kx, m_blk, mb);
        }
        pdl_wait();
#pragma unroll
        for (int t = 0; t < NSTAGE; t++) {
            uint32_t mb = smaddr(mbar + t);
            unsigned char* sp = data + (size_t)t * STAGE_BYTES;
            int kx = kbeg + t * BKT;
            tma2d(smaddr(sp + 2*A_LIMB_BYTES),                &mB0, kx, 0, mb);
            tma2d(smaddr(sp + 2*A_LIMB_BYTES + B_LIMB_BYTES), &mB1, kx, 0, mb);
        }
    }
    pdl_trigger();   // dependents' pre-wait part touches only weights/smem

    auto issue = [&](int t, int st) {
        uint32_t mb = smaddr(mbar + st);
        asm volatile("mbarrier.arrive.expect_tx.shared.b64 _, [%0], %1;"
                     :: "r"(mb), "r"((uint32_t)STAGE_BYTES) : "memory");
        unsigned char* sp = data + (size_t)st * STAGE_BYTES;
        int kx = kbeg + t * BKT;
        tma2d(smaddr(sp),                                   &mA0, kx, m_blk, mb);
        tma2d(smaddr(sp + A_LIMB_BYTES),                    &mA1, kx, m_blk, mb);
        tma2d(smaddr(sp + 2*A_LIMB_BYTES),                  &mB0, kx, 0,     mb);
        tma2d(smaddr(sp + 2*A_LIMB_BYTES + B_LIMB_BYTES),   &mB1, kx, 0,     mb);
    };

    float d[2][4][4];
#pragma unroll
    for (int i = 0; i < 2; i++)
#pragma unroll
        for (int j = 0; j < 4; j++)
#pragma unroll
            for (int q = 0; q < 4; q++) d[i][j][q] = 0.0f;

    for (int t = 0; t < ntiles; t++) {
        int st = t & 1;
        int ph = (t >> 1) & 1;
        mbar_wait(smaddr(mbar + st), ph);

        const unsigned char* sp = data + (size_t)st * STAGE_BYTES;
        const unsigned char* A0s = sp;
        const unsigned char* A1s = sp + A_LIMB_BYTES;
        const unsigned char* B0s = sp + 2*A_LIMB_BYTES;
        const unsigned char* B1s = B0s + B_LIMB_BYTES;

#pragma unroll
        for (int ks = 0; ks < BKT; ks += 16) {
            uint32_t af[2][2][4];   // [mtile][limb][4]
#pragma unroll
            for (int mt = 0; mt < 2; mt++) {
                int row = wm + mt * 16 + ((lane >> 3) & 1) * 8 + (lane & 7);
                uint32_t off = swz((uint32_t)row * 128 + (ks + (lane >> 4) * 8) * 2);
                uint32_t a0 = smaddr(A0s + off);
                asm volatile("ldmatrix.sync.aligned.m8n8.x4.shared.b16 {%0,%1,%2,%3},[%4];"
                    : "=r"(af[mt][0][0]), "=r"(af[mt][0][1]),
                      "=r"(af[mt][0][2]), "=r"(af[mt][0][3]) : "r"(a0));
                uint32_t a1 = smaddr(A1s + off);
                asm volatile("ldmatrix.sync.aligned.m8n8.x4.shared.b16 {%0,%1,%2,%3},[%4];"
                    : "=r"(af[mt][1][0]), "=r"(af[mt][1][1]),
                      "=r"(af[mt][1][2]), "=r"(af[mt][1][3]) : "r"(a1));
            }
            uint32_t bf[2][8];      // [limb][nt*4 + r]
#pragma unroll
            for (int nt = 0; nt < 2; nt++) {
                int row = wn + nt * 16 + (lane >> 4) * 8 + (lane & 7);
                uint32_t off = swz((uint32_t)row * 128 + (ks + ((lane >> 3) & 1) * 8) * 2);
                uint32_t b0 = smaddr(B0s + off);
                asm volatile("ldmatrix.sync.aligned.m8n8.x4.shared.b16 {%0,%1,%2,%3},[%4];"
                    : "=r"(bf[0][nt * 4 + 0]), "=r"(bf[0][nt * 4 + 1]),
                      "=r"(bf[0][nt * 4 + 2]), "=r"(bf[0][nt * 4 + 3]) : "r"(b0));
                uint32_t b1 = smaddr(B1s + off);
                asm volatile("ldmatrix.sync.aligned.m8n8.x4.shared.b16 {%0,%1,%2,%3},[%4];"
                    : "=r"(bf[1][nt * 4 + 0]), "=r"(bf[1][nt * 4 + 1]),
                      "=r"(bf[1][nt * 4 + 2]), "=r"(bf[1][nt * 4 + 3]) : "r"(b1));
            }
#pragma unroll
            for (int mt = 0; mt < 2; mt++) {
#pragma unroll
                for (int j = 0; j < 4; j++) {
                    float* dd = d[mt][j];
                    uint32_t b00 = bf[0][j * 2], b01 = bf[0][j * 2 + 1];
                    uint32_t b10 = bf[1][j * 2], b11 = bf[1][j * 2 + 1];
                    MMA_16816(dd, af[mt][0], b00, b01);   // w0*b0
                    MMA_16816(dd, af[mt][0], b10, b11);   // w0*b1
                    MMA_16816(dd, af[mt][1], b00, b01);   // w1*b0
                }
            }
        }
        __syncthreads();
        if (tid == 0 && t + NSTAGE < ntiles) issue(t + NSTAGE, st);
    }

    float* Cz = Cbuf + (size_t)blockIdx.z * Mtot * NB;
#pragma unroll
    for (int mt = 0; mt < 2; mt++) {
#pragma unroll
        for (int j = 0; j < 4; j++) {
            int r = m_blk + wm + mt * 16 + (lane >> 2);
            int c = wn + j * 8 + (lane & 3) * 2;
            *(float2*)&Cz[(size_t)r * NB + c]       = make_float2(d[mt][j][0], d[mt][j][1]);
            *(float2*)&Cz[(size_t)(r + 8) * NB + c] = make_float2(d[mt][j][2], d[mt][j][3]);
        }
    }
}

// ---------------- epilogue (two-phase, proven in R10; + PDL) ----------------
__global__ __launch_bounds__(256)
void epi(const float* __restrict__ Cbuf, int S, int F,
         const float* __restrict__ bias,
         float* __restrict__ stateF,
         __half* __restrict__ S0, __half* __restrict__ S1, int colBase,
         int step, const int* __restrict__ steps_ptr,
         float* __restrict__ finout) {
    __shared__ float nvs[16][65];
    const int t = threadIdx.x;
    const int f0 = blockIdx.x * 16;

    pdl_wait();      // D / state produced by predecessor
    pdl_trigger();   // successor's pre-wait part touches only weights/smem

    float stepsf = (float)(*steps_ptr);
    float temp = 0.01f * (1.0f + 4.0f * expf((-5.0f * (float)step) / stepsf));

    {
        int fl = t >> 4;
        int b4 = (t & 15) * 4;
        int f = f0 + fl;
        const float* cb = Cbuf + (size_t)f * NB + b4;
        float4 s = make_float4(0.f, 0.f, 0.f, 0.f);
        for (int z = 0; z < S; z++) {
            float4 v = *(const float4*)(cb + (size_t)z * F * NB);
            s.x += v.x; s.y += v.y; s.z += v.z; s.w += v.w;
        }
        float bi = bias[f];
        s.x = s.x * INV_WSCALE + bi; s.y = s.y * INV_WSCALE + bi;
        s.z = s.z * INV_WSCALE + bi; s.w = s.w * INV_WSCALE + bi;
        float4 old = *(const float4*)&stateF[(size_t)f * NB + b4];
        float4 nv;
        nv.x = 0.9f * old.x + 0.1f / (1.0f + expf(-s.x / temp));
        nv.y = 0.9f * old.y + 0.1f / (1.0f + expf(-s.y / temp));
        nv.z = 0.9f * old.z + 0.1f / (1.0f + expf(-s.z / temp));
        nv.w = 0.9f * old.w + 0.1f / (1.0f + expf(-s.w / temp));
        *(float4*)&stateF[(size_t)f * NB + b4] = nv;
        nvs[fl][b4 + 0] = nv.x;
        nvs[fl][b4 + 1] = nv.y;
        nvs[fl][b4 + 2] = nv.z;
        nvs[fl][b4 + 3] = nv.w;
    }
    __syncthreads();

    {
        int b = t >> 2;
        int fo = (t & 3) * 4;
        float v0 = nvs[fo + 0][b], v1 = nvs[fo + 1][b];
        float v2 = nvs[fo + 2][b], v3 = nvs[fo + 3][b];
        __half h00 = __float2half_rn(v0), h01 = __float2half_rn(v1);
        __half h02 = __float2half_rn(v2), h03 = __float2half_rn(v3);
        __half r0 = __float2half_rn(v0 - __half2float(h00));
        __half r1 = __float2half_rn(v1 - __half2float(h01));
        __half r2 = __float2half_rn(v2 - __half2float(h02));
        __half r3 = __float2half_rn(v3 - __half2float(h03));
        size_t base = (size_t)b * KTOT + colBase + f0 + fo;
        *(__half2*)&S0[base]     = __halves2half2(h00, h01);
        *(__half2*)&S0[base + 2] = __halves2half2(h02, h03);
        *(__half2*)&S1[base]     = __halves2half2(r0, r1);
        *(__half2*)&S1[base + 2] = __halves2half2(r2, r3);
        if (finout) {
            *(float4*)&finout[(size_t)b * F + f0 + fo] = make_float4(v0, v1, v2, v3);
        }
    }
}

// ---------------- host: tensor map encode ----------------
typedef CUresult (*EncodeTiledFn)(
    CUtensorMap*, CUtensorMapDataType, cuuint32_t, void*,
    const cuuint64_t*, const cuuint64_t*, const cuuint32_t*, const cuuint32_t*,
    CUtensorMapInterleave, CUtensorMapSwizzle, CUtensorMapL2promotion,
    CUtensorMapFloatOOBfill);

static EncodeTiledFn get_encoder() {
    void* fp = nullptr;
#if CUDART_VERSION >= 12050
    cudaDriverEntryPointQueryResult st;
    cudaGetDriverEntryPointByVersion("cuTensorMapEncodeTiled", &fp, 12000,
                                     cudaEnableDefault, &st);
#else
    cudaDriverEntryPointQueryResult st;
    cudaGetDriverEntryPoint("cuTensorMapEncodeTiled", &fp, cudaEnableDefault, &st);
#endif
    return (EncodeTiledFn)fp;
}

static void make_map(EncodeTiledFn enc, CUtensorMap* m, void* ptr,
                     uint64_t rows, uint32_t boxRows) {
    cuuint64_t dims[2]    = {(cuuint64_t)KTOT, (cuuint64_t)rows};
    cuuint64_t strides[1] = {(cuuint64_t)KTOT * sizeof(__half)};
    cuuint32_t box[2]     = {BKT, boxRows};
    cuuint32_t es[2]      = {1, 1};
    enc(m, CU_TENSOR_MAP_DATA_TYPE_FLOAT16, 2, ptr, dims, strides, box, es,
        CU_TENSOR_MAP_INTERLEAVE_NONE, CU_TENSOR_MAP_SWIZZLE_128B,
        CU_TENSOR_MAP_L2_PROMOTION_L2_128B, CU_TENSOR_MAP_FLOAT_OOB_FILL_NONE);
}

// ---------------- host launcher ----------------
extern "C" void kernel_launch(void* const* d_in, const int* in_sizes, int n_in,
                              void* d_out, int out_size) {
    const float* x        = (const float*)d_in[0];
    const float* vis_bias = (const float*)d_in[1];
    const float* hid_bias = (const float*)d_in[2];
    const float* vis_hid  = (const float*)d_in[3];
    const float* vv_raw   = (const float*)d_in[4];
    const float* hh_raw   = (const float*)d_in[5];
    const int*   steps_p  = (const int*)d_in[6];

    __half *Wv0, *Wv1, *Wh0, *Wh1, *S0, *S1;
    float *visF, *hidF, *D1, *D2;
    cudaGetSymbolAddress((void**)&Wv0, g_Wv0); cudaGetSymbolAddress((void**)&Wv1, g_Wv1);
    cudaGetSymbolAddress((void**)&Wh0, g_Wh0); cudaGetSymbolAddress((void**)&Wh1, g_Wh1);
    cudaGetSymbolAddress((void**)&S0, g_S0);   cudaGetSymbolAddress((void**)&S1, g_S1);
    cudaGetSymbolAddress((void**)&visF, g_visF); cudaGetSymbolAddress((void**)&hidF, g_hidF);
    cudaGetSymbolAddress((void**)&D1, g_D1);   cudaGetSymbolAddress((void**)&D2, g_D2);

    EncodeTiledFn enc = get_encoder();
    CUtensorMap mWv0, mWv1, mWh0, mWh1, mS0, mS1;
    make_map(enc, &mWv0, Wv0, VS, MT);
    make_map(enc, &mWv1, Wv1, VS, MT);
    make_map(enc, &mWh0, Wh0, HS, MT);
    make_map(enc, &mWh1, Wh1, HS, MT);
    make_map(enc, &mS0,  S0,  NB, NB);
    make_map(enc, &mS1,  S1,  NB, NB);

    const int SMEM = 1024 + NSTAGE * STAGE_BYTES;   // 99328
    cudaFuncSetAttribute(gemm_tma, cudaFuncAttributeMaxDynamicSharedMemorySize, SMEM);

    k_sym_split<<<dim3(VS / 32, VS / 32), dim3(32, 8)>>>(vv_raw, VS, Wv0, Wv1, 0);
    k_sym_split<<<dim3(HS / 32, HS / 32), dim3(32, 8)>>>(hh_raw, HS, Wh0, Wh1, VS);
    k_vh_split<<<dim3(HS / 32, VS / 32), dim3(32, 8)>>>(vis_hid, Wv0, Wv1, Wh0, Wh1);
    k_init<<<(NB * VS + 255) / 256, 256>>>(x, visF, hidF, S0, S1);

    // PDL launch attribute (single stream 0 — graph stays linear, nodes get
    // programmatic-serialization edges; no extra graph branches/allocations)
    cudaLaunchAttribute pdlAttr[1];
    pdlAttr[0].id = cudaLaunchAttributeProgrammaticStreamSerialization;
    pdlAttr[0].val.programmaticStreamSerializationAllowed = 1;

    for (int i = 0; i < STEPS; i++) {
        // hidden update GEMM
        {
            cudaLaunchConfig_t cfg = {};
            cfg.gridDim = dim3(HS / MT, 1, SPLIT_H);
            cfg.blockDim = dim3(256, 1, 1);
            cfg.dynamicSmemBytes = SMEM;
            cfg.stream = 0;
            cfg.attrs = pdlAttr; cfg.numAttrs = 1;
            cudaLaunchKernelEx(&cfg, gemm_tma, mWh0, mWh1, mS0, mS1,
                               D1, (int)HS, (int)(KTOT / SPLIT_H));
        }
        // hidden epilogue
        {
            cudaLaunchConfig_t cfg = {};
            cfg.gridDim = dim3(HS / 16, 1, 1);
            cfg.blockDim = dim3(256, 1, 1);
            cfg.dynamicSmemBytes = 0;
            cfg.stream = 0;
            cfg.attrs = pdlAttr; cfg.numAttrs = 1;
            cudaLaunchKernelEx(&cfg, epi, (const float*)D1, (int)SPLIT_H, (int)HS,
                               hid_bias, hidF, S0, S1, (int)VS, i, steps_p,
                               (float*)nullptr);
        }
        // visible update GEMM
        {
            cudaLaunchConfig_t cfg = {};
            cfg.gridDim = dim3(VS / MT, 1, SPLIT_V);
            cfg.blockDim = dim3(256, 1, 1);
            cfg.dynamicSmemBytes = SMEM;
            cfg.stream = 0;
            cfg.attrs = pdlAttr; cfg.numAttrs = 1;
            cudaLaunchKernelEx(&cfg, gemm_tma, mWv0, mWv1, mS0, mS1,
                               D2, (int)VS, (int)(KTOT / SPLIT_V));
        }
        // visible epilogue
        {
            cudaLaunchConfig_t cfg = {};
            cfg.gridDim = dim3(VS / 16, 1, 1);
            cfg.blockDim = dim3(256, 1, 1);
            cfg.dynamicSmemBytes = 0;
            cfg.stream = 0;
            cfg.attrs = pdlAttr; cfg.numAttrs = 1;
            cudaLaunchKernelEx(&cfg, epi, (const float*)D2, (int)SPLIT_V, (int)VS,
                               vis_bias, visF, S0, S1, 0, i, steps_p,
                               (i == STEPS - 1) ? (float*)d_out : (float*)nullptr);
        }
    }
}